// round 14
// baseline (speedup 1.0000x reference)
#include <cuda_runtime.h>
#include <cuda_fp16.h>
#include <math.h>
#include <stdint.h>

// Problem constants (fixed by the dataset)
#define T_TOK 4096
#define HID   1024
#define NE    16
#define FE    512
#define FS    2048
#define NPAIR (T_TOK * 2)

// ---------------------------------------------------------------------------
// Scratch (all half2-packed words are uint32)
// ---------------------------------------------------------------------------
__device__ float    g_gate_s[(size_t)T_TOK * FS];
__device__ float    g_gate_r[(size_t)NPAIR * FE];
__device__ int      g_cnt[NE];
__device__ int      g_bucket[NE * T_TOK];
__device__ float    g_pw[NPAIR];
// pre-split A-side (rows x K/2 words, contiguous k)
__device__ uint32_t g_xh[(size_t)T_TOK * HID / 2];
__device__ uint32_t g_xl[(size_t)T_TOK * HID / 2];
// pre-split B-side, N-MAJOR: [n][K/2 words]
__device__ uint32_t g_sgh[(size_t)FS * HID / 2],  g_sgl[(size_t)FS * HID / 2];
__device__ uint32_t g_suh[(size_t)FS * HID / 2],  g_sul[(size_t)FS * HID / 2];
__device__ uint32_t g_sdh[(size_t)HID * FS / 2],  g_sdl[(size_t)HID * FS / 2];
__device__ uint32_t g_egh[(size_t)NE * FE * HID / 2], g_egl[(size_t)NE * FE * HID / 2];
__device__ uint32_t g_euh[(size_t)NE * FE * HID / 2], g_eul[(size_t)NE * FE * HID / 2];
__device__ uint32_t g_edh[(size_t)NE * HID * FE / 2], g_edl[(size_t)NE * HID * FE / 2];
// pre-split intermediates (A-side packing, written by FUSE epilogues)
__device__ uint32_t g_ish[(size_t)T_TOK * FS / 2],  g_isl[(size_t)T_TOK * FS / 2];
__device__ uint32_t g_irh[(size_t)NPAIR * FE / 2],  g_irl[(size_t)NPAIR * FE / 2];

// ---------------------------------------------------------------------------
// fp16 hi/lo split (validated R10-R13)
// ---------------------------------------------------------------------------
__device__ __forceinline__ void split_h2(float x, float y,
                                         uint32_t& hi, uint32_t& lo) {
    half hx = __float2half_rn(x);
    half hy = __float2half_rn(y);
    half lx = __float2half_rn(x - __half2float(hx));
    half ly = __float2half_rn(y - __half2float(hy));
    __half2 h = __halves2half2(hx, hy);
    __half2 l = __halves2half2(lx, ly);
    hi = *reinterpret_cast<uint32_t*>(&h);
    lo = *reinterpret_cast<uint32_t*>(&l);
}

__device__ __forceinline__ void mma_f16(float* d,
                                        const uint32_t* a,
                                        const uint32_t* b) {
    asm volatile(
        "mma.sync.aligned.m16n8k16.row.col.f32.f16.f16.f32 "
        "{%0,%1,%2,%3}, {%4,%5,%6,%7}, {%8,%9}, {%0,%1,%2,%3};\n"
        : "+f"(d[0]), "+f"(d[1]), "+f"(d[2]), "+f"(d[3])
        : "r"(a[0]), "r"(a[1]), "r"(a[2]), "r"(a[3]),
          "r"(b[0]), "r"(b[1]));
}

#define LDSM_X4(r0, r1, r2, r3, addr) \
    asm volatile("ldmatrix.sync.aligned.m8n8.x4.shared.b16 {%0,%1,%2,%3}, [%4];" \
                 : "=r"(r0), "=r"(r1), "=r"(r2), "=r"(r3) : "r"(addr))

__device__ __forceinline__ void cp_async16(uint32_t dst, const void* src,
                                           int src_bytes) {
    asm volatile("cp.async.cg.shared.global [%0], [%1], 16, %2;\n"
                 :: "r"(dst), "l"(src), "r"(src_bytes) : "memory");
}
#define CP_COMMIT() asm volatile("cp.async.commit_group;" ::: "memory")
#define CP_WAIT2()  asm volatile("cp.async.wait_group 2;" ::: "memory")

__device__ __forceinline__ uint32_t cvta_smem(const void* p) {
    uint32_t a;
    asm("{ .reg .u64 t; cvta.to.shared.u64 t, %1; cvt.u32.u64 %0, t; }"
        : "=r"(a) : "l"(p));
    return a;
}

// ---------------------------------------------------------------------------
// Splitters
// ---------------------------------------------------------------------------
// A-side: pairs along contiguous dim (x only)
__global__ void split_contig_kernel(const float* __restrict__ src,
                                    uint32_t* __restrict__ hi,
                                    uint32_t* __restrict__ lo, int nwords) {
    int i = (blockIdx.x * 256 + threadIdx.x) * 4;
    if (i >= nwords) return;
    float2 v0 = ((const float2*)src)[i];
    float2 v1 = ((const float2*)src)[i + 1];
    float2 v2 = ((const float2*)src)[i + 2];
    float2 v3 = ((const float2*)src)[i + 3];
    uint4 h, l;
    split_h2(v0.x, v0.y, h.x, l.x);
    split_h2(v1.x, v1.y, h.y, l.y);
    split_h2(v2.x, v2.y, h.z, l.z);
    split_h2(v3.x, v3.y, h.w, l.w);
    *(uint4*)(hi + i) = h;
    *(uint4*)(lo + i) = l;
}
// B-side TRANSPOSING splitter: src [2*KW][N] (k-major, one expert per bIdx.z)
// -> out [N][KW] n-major: word(n, kp) = half2(src[2kp][n], src[2kp+1][n]).
// thread: n = idx % N (coalesced reads), kq = (idx / N)*4 (16B write).
__global__ void split_transpose_kernel(const float* __restrict__ src,
                                       uint32_t* __restrict__ hi,
                                       uint32_t* __restrict__ lo,
                                       int N, int KW) {
    src += (size_t)blockIdx.z * 2 * KW * N;
    hi  += (size_t)blockIdx.z * (size_t)N * KW;
    lo  += (size_t)blockIdx.z * (size_t)N * KW;
    int idx = blockIdx.x * 256 + threadIdx.x;
    if (idx >= N * (KW / 4)) return;
    int n  = idx % N;
    int kq = (idx / N) * 4;
    uint4 h, l;
#pragma unroll
    for (int j = 0; j < 4; j++) {
        float a = src[(size_t)(2 * (kq + j)) * N + n];
        float b = src[(size_t)(2 * (kq + j) + 1) * N + n];
        uint32_t hh, ll;
        split_h2(a, b, hh, ll);
        ((uint32_t*)&h)[j] = hh;
        ((uint32_t*)&l)[j] = ll;
    }
    *(uint4*)(hi + (size_t)n * KW + kq) = h;
    *(uint4*)(lo + (size_t)n * KW + kq) = l;
}

// ---------------------------------------------------------------------------
// Router (validated rounds 1-13)
// ---------------------------------------------------------------------------
__global__ void zero_counts_kernel() {
    if (threadIdx.x < NE) g_cnt[threadIdx.x] = 0;
}

__global__ void router_kernel(const float* __restrict__ x,
                              const float* __restrict__ rw) {
    int warp = threadIdx.x >> 5;
    int lane = threadIdx.x & 31;
    int t = blockIdx.x * (blockDim.x >> 5) + warp;
    if (t >= T_TOK) return;

    float acc[NE];
#pragma unroll
    for (int e = 0; e < NE; e++) acc[e] = 0.0f;

    const float* xr = x + (size_t)t * HID;
    for (int d = lane; d < HID; d += 32) {
        float xv = xr[d];
        const float* r = rw + (size_t)d * NE;
#pragma unroll
        for (int e = 0; e < NE; e++) acc[e] = fmaf(xv, r[e], acc[e]);
    }
#pragma unroll
    for (int e = 0; e < NE; e++) {
#pragma unroll
        for (int off = 16; off; off >>= 1)
            acc[e] += __shfl_xor_sync(0xffffffffu, acc[e], off);
    }

    if (lane == 0) {
        float mx = acc[0];
#pragma unroll
        for (int e = 1; e < NE; e++) mx = fmaxf(mx, acc[e]);
        float p[NE];
        float s = 0.0f;
#pragma unroll
        for (int e = 0; e < NE; e++) { p[e] = expf(acc[e] - mx); s += p[e]; }
        float inv = 1.0f / s;
#pragma unroll
        for (int e = 0; e < NE; e++) p[e] *= inv;

        int   i0 = 0; float w0 = p[0];
#pragma unroll
        for (int e = 1; e < NE; e++) if (p[e] > w0) { w0 = p[e]; i0 = e; }
        int   i1 = -1; float w1 = -1.0f;
#pragma unroll
        for (int e = 0; e < NE; e++)
            if (e != i0 && p[e] > w1) { w1 = p[e]; i1 = e; }

        int pos0 = atomicAdd(&g_cnt[i0], 1);
        g_bucket[i0 * T_TOK + pos0] = 2 * t;
        int pos1 = atomicAdd(&g_cnt[i1], 1);
        g_bucket[i1 * T_TOK + pos1] = 2 * t + 1;
        g_pw[2 * t]     = w0;
        g_pw[2 * t + 1] = w1;
    }
}

// ---------------------------------------------------------------------------
// Tensor GEMM 128x128x16, 256 threads, pre-split fp16, cp.async 4-stage,
// m16n8k16 HMMA. BOTH operands via ldmatrix.x4 from [row][12]-stride smem
// (rows: A=m, B=n; stride-12 LDSM + producer stores verified conflict-free:
//  8-row phases start at {0,12,24,4,16,28,8,20} mod 32).
// Producers: 1 thread per (row, hi/lo); 2x cp.async16 per operand.
// MODE 0: plain. MODE 1: gather x rows by pair>>1, scatter C by pair.
// MODE 2: gather rows by pair, scale by router weight, atomicAdd into C[token].
// FUSE 1: write CH/CL = split(silu(G) * acc) instead of C.
// ---------------------------------------------------------------------------
#define BM 128
#define BN 128
#define BK 16
#define A_PAD 12
#define OFF_AL 1536
#define OFF_BH 3072
#define OFF_BL 4608
#define STAGEF 6144
#define NSTG 4
#define SMEM_DYN (NSTG * STAGEF * 4)

template <int MODE, int FUSE>
__global__ __launch_bounds__(256, 2)
void tgemm_kernel(const uint32_t* __restrict__ Ahg,
                  const uint32_t* __restrict__ Alg,
                  const uint32_t* __restrict__ Bhg,
                  const uint32_t* __restrict__ Blg,
                  float* __restrict__ C,
                  uint32_t* __restrict__ CH,
                  uint32_t* __restrict__ CL,
                  const float* __restrict__ G,
                  int M, int N, int K) {
    const int e = blockIdx.z;
    int m_rows = M;
    const int* rowlist = nullptr;
    const int KW = K / 2;
    if (MODE != 0) {
        m_rows  = g_cnt[e];
        rowlist = g_bucket + e * T_TOK;
        Bhg += (size_t)e * N * KW;   // n-major per-expert block
        Blg += (size_t)e * N * KW;
    }
    const int m0 = blockIdx.y * BM;
    const int n0 = blockIdx.x * BN;
    if (m0 >= m_rows) return;

    extern __shared__ uint32_t sm[];
    const uint32_t smem_base = cvta_smem(sm);

    const int tid  = threadIdx.x;
    const int lane = tid & 31;
    const int wid  = tid >> 5;
    const int warp_m = wid >> 2;
    const int warp_n = wid & 3;
    const int g  = lane >> 2;
    const int t4 = lane & 3;
    const int mb = warp_m * 64;
    const int nb = warp_n * 32;

    // --- producers: 1 thread per (row, hi/lo); rows 0..127 ---
    const int prow = tid & 127;
    const int phl  = tid >> 7;       // 0 = hi, 1 = lo

    const int  ar_g = m0 + prow;
    const bool av   = ar_g < m_rows;
    const int  aidx = av ? ar_g : 0;
    int rowidx;
    if (MODE == 0)      rowidx = aidx;
    else if (MODE == 1) rowidx = rowlist[aidx] >> 1;
    else                rowidx = rowlist[aidx];
    const uint32_t* Asrc = (phl ? Alg : Ahg) + (size_t)rowidx * KW;
    const uint32_t* Bsrc = (phl ? Blg : Bhg) + (size_t)(n0 + prow) * KW;
    const int abytes = av ? 16 : 0;

    const uint32_t a_dst = smem_base + (phl * OFF_AL + prow * A_PAD) * 4;
    const uint32_t b_dst = smem_base + (OFF_BH + phl * (OFF_BL - OFF_BH)
                                        + prow * A_PAD) * 4;
    const int KT = K / BK;

    auto issue_stage = [&](int kt) {
        const uint32_t so = (uint32_t)((kt % NSTG) * (STAGEF * 4));
        const int kw0 = kt * 8;
        cp_async16(a_dst + so,      Asrc + kw0,     abytes);
        cp_async16(a_dst + so + 16, Asrc + kw0 + 4, abytes);
        cp_async16(b_dst + so,      Bsrc + kw0,     16);
        cp_async16(b_dst + so + 16, Bsrc + kw0 + 4, 16);
    };

    // ldmatrix lane addressing
    const int sel = lane >> 3;          // tile index within x4
    const int rr  = lane & 7;
    // A: tiles (m-lo k-lo, m-hi k-lo, m-lo k-hi, m-hi k-hi)
    const uint32_t a_lm_base =
        (uint32_t)(((mb + rr + ((sel & 1) << 3)) * A_PAD + ((sel >> 1) << 2)) * 4);
    // B: tiles (nt k-lo, nt k-hi, nt+1 k-lo, nt+1 k-hi) per pair p
    const uint32_t b_lm_base =
        (uint32_t)((OFF_BH + (nb + ((sel >> 1) << 3) + rr) * A_PAD
                    + ((sel & 1) << 2)) * 4);

    issue_stage(0); CP_COMMIT();
    issue_stage(1); CP_COMMIT();
    issue_stage(2); CP_COMMIT();

    float acc[4][4][4];
#pragma unroll
    for (int i = 0; i < 4; i++)
#pragma unroll
        for (int j = 0; j < 4; j++)
#pragma unroll
            for (int r = 0; r < 4; r++) acc[i][j][r] = 0.0f;

    for (int kt = 0; kt < KT; kt++) {
        CP_WAIT2();
        __syncthreads();
        if (kt + 3 < KT) issue_stage(kt + 3);
        CP_COMMIT();

        const uint32_t stage_b = smem_base + (uint32_t)((kt % NSTG) * (STAGEF * 4));

        // B fragments: 2 LDSM.x4 per hi/lo (pairs of nt)
        uint32_t bh[4][2], bl[4][2];
#pragma unroll
        for (int p = 0; p < 2; p++) {
            const uint32_t addr = stage_b + b_lm_base
                                + (uint32_t)(p * 16 * A_PAD * 4);
            LDSM_X4(bh[2 * p][0], bh[2 * p][1], bh[2 * p + 1][0], bh[2 * p + 1][1],
                    addr);
            LDSM_X4(bl[2 * p][0], bl[2 * p][1], bl[2 * p + 1][0], bl[2 * p + 1][1],
                    addr + (OFF_BL - OFF_BH) * 4);
        }
#pragma unroll
        for (int mt = 0; mt < 4; mt++) {
            const uint32_t a_addr = stage_b + a_lm_base
                                  + (uint32_t)(mt * 16 * A_PAD * 4);
            uint32_t ah[4], al[4];
            LDSM_X4(ah[0], ah[1], ah[2], ah[3], a_addr);
            LDSM_X4(al[0], al[1], al[2], al[3], a_addr + OFF_AL * 4);
#pragma unroll
            for (int nt = 0; nt < 4; nt++) mma_f16(acc[mt][nt], ah, bh[nt]);
#pragma unroll
            for (int nt = 0; nt < 4; nt++) mma_f16(acc[mt][nt], ah, bl[nt]);
#pragma unroll
            for (int nt = 0; nt < 4; nt++) mma_f16(acc[mt][nt], al, bh[nt]);
        }
    }

    // Epilogue (validated R12/R13)
#pragma unroll
    for (int mt = 0; mt < 4; mt++) {
        const int r0 = m0 + mb + mt * 16 + g;
        const int r1 = r0 + 8;
        size_t ro0 = 0, ro1 = 0;
        bool v0 = r0 < m_rows, v1 = r1 < m_rows;
        float s0 = 1.0f, s1 = 1.0f;
        if (v0) {
            if (MODE == 0) ro0 = (size_t)r0 * N;
            else {
                const int p = rowlist[r0];
                if (MODE == 2) { s0 = g_pw[p]; ro0 = (size_t)(p >> 1) * N; }
                else ro0 = (size_t)p * N;
            }
        }
        if (v1) {
            if (MODE == 0) ro1 = (size_t)r1 * N;
            else {
                const int p = rowlist[r1];
                if (MODE == 2) { s1 = g_pw[p]; ro1 = (size_t)(p >> 1) * N; }
                else ro1 = (size_t)p * N;
            }
        }
#pragma unroll
        for (int nt = 0; nt < 4; nt++) {
            const int c = n0 + nb + nt * 8 + 2 * t4;
            if (v0) {
                float o0 = acc[mt][nt][0] * s0, o1 = acc[mt][nt][1] * s0;
                if (FUSE) {
                    float2 gv = *(const float2*)(G + ro0 + c);
                    o0 *= gv.x / (1.0f + expf(-gv.x));
                    o1 *= gv.y / (1.0f + expf(-gv.y));
                    uint32_t h, l;
                    split_h2(o0, o1, h, l);
                    const size_t wi = (ro0 + c) >> 1;
                    CH[wi] = h; CL[wi] = l;
                } else if (MODE == 2) {
                    atomicAdd(C + ro0 + c, o0);
                    atomicAdd(C + ro0 + c + 1, o1);
                } else {
                    *(float2*)(C + ro0 + c) = make_float2(o0, o1);
                }
            }
            if (v1) {
                float o0 = acc[mt][nt][2] * s1, o1 = acc[mt][nt][3] * s1;
                if (FUSE) {
                    float2 gv = *(const float2*)(G + ro1 + c);
                    o0 *= gv.x / (1.0f + expf(-gv.x));
                    o1 *= gv.y / (1.0f + expf(-gv.y));
                    uint32_t h, l;
                    split_h2(o0, o1, h, l);
                    const size_t wi = (ro1 + c) >> 1;
                    CH[wi] = h; CL[wi] = l;
                } else if (MODE == 2) {
                    atomicAdd(C + ro1 + c, o0);
                    atomicAdd(C + ro1 + c + 1, o1);
                } else {
                    *(float2*)(C + ro1 + c) = make_float2(o0, o1);
                }
            }
        }
    }
}

// ---------------------------------------------------------------------------
// Launch
// ---------------------------------------------------------------------------
extern "C" void kernel_launch(void* const* d_in, const int* in_sizes, int n_in,
                              void* d_out, int out_size) {
    const float* x  = (const float*)d_in[0];
    const float* rw = (const float*)d_in[1];
    const float* eg = (const float*)d_in[2];
    const float* eu = (const float*)d_in[3];
    const float* ed = (const float*)d_in[4];
    const float* sg = (const float*)d_in[5];
    const float* su = (const float*)d_in[6];
    const float* sd = (const float*)d_in[7];
    float* out = (float*)d_out;

#define SYM(p, s) void* p; cudaGetSymbolAddress(&p, s)
    SYM(p_gate_s, g_gate_s); SYM(p_gate_r, g_gate_r);
    SYM(p_xh, g_xh);   SYM(p_xl, g_xl);
    SYM(p_sgh, g_sgh); SYM(p_sgl, g_sgl);
    SYM(p_suh, g_suh); SYM(p_sul, g_sul);
    SYM(p_sdh, g_sdh); SYM(p_sdl, g_sdl);
    SYM(p_egh, g_egh); SYM(p_egl, g_egl);
    SYM(p_euh, g_euh); SYM(p_eul, g_eul);
    SYM(p_edh, g_edh); SYM(p_edl, g_edl);
    SYM(p_ish, g_ish); SYM(p_isl, g_isl);
    SYM(p_irh, g_irh); SYM(p_irl, g_irl);
#undef SYM

    cudaFuncSetAttribute(tgemm_kernel<0, 0>,
                         cudaFuncAttributeMaxDynamicSharedMemorySize, SMEM_DYN);
    cudaFuncSetAttribute(tgemm_kernel<0, 1>,
                         cudaFuncAttributeMaxDynamicSharedMemorySize, SMEM_DYN);
    cudaFuncSetAttribute(tgemm_kernel<1, 0>,
                         cudaFuncAttributeMaxDynamicSharedMemorySize, SMEM_DYN);
    cudaFuncSetAttribute(tgemm_kernel<1, 1>,
                         cudaFuncAttributeMaxDynamicSharedMemorySize, SMEM_DYN);
    cudaFuncSetAttribute(tgemm_kernel<2, 0>,
                         cudaFuncAttributeMaxDynamicSharedMemorySize, SMEM_DYN);

    zero_counts_kernel<<<1, 32>>>();
    router_kernel<<<T_TOK / 4, 128>>>(x, rw);

    // Pre-split. A-side: contiguous. B-side: transposing (n-major out).
    split_contig_kernel<<<(T_TOK * HID / 2 / 4) / 256, 256>>>(
        x, (uint32_t*)p_xh, (uint32_t*)p_xl, T_TOK * HID / 2);
    split_transpose_kernel<<<dim3((FS * (HID / 2 / 4)) / 256, 1, 1), 256>>>(
        sg, (uint32_t*)p_sgh, (uint32_t*)p_sgl, FS, HID / 2);
    split_transpose_kernel<<<dim3((FS * (HID / 2 / 4)) / 256, 1, 1), 256>>>(
        su, (uint32_t*)p_suh, (uint32_t*)p_sul, FS, HID / 2);
    split_transpose_kernel<<<dim3((HID * (FS / 2 / 4)) / 256, 1, 1), 256>>>(
        sd, (uint32_t*)p_sdh, (uint32_t*)p_sdl, HID, FS / 2);
    split_transpose_kernel<<<dim3((FE * (HID / 2 / 4)) / 256, 1, NE), 256>>>(
        eg, (uint32_t*)p_egh, (uint32_t*)p_egl, FE, HID / 2);
    split_transpose_kernel<<<dim3((FE * (HID / 2 / 4)) / 256, 1, NE), 256>>>(
        eu, (uint32_t*)p_euh, (uint32_t*)p_eul, FE, HID / 2);
    split_transpose_kernel<<<dim3((HID * (FE / 2 / 4)) / 256, 1, NE), 256>>>(
        ed, (uint32_t*)p_edh, (uint32_t*)p_edl, HID, FE / 2);

    // Shared expert: gate -> (up, silu fused, split-write) -> down (writes out)
    tgemm_kernel<0, 0><<<dim3(FS / BN, T_TOK / BM, 1), 256, SMEM_DYN>>>(
        (const uint32_t*)p_xh, (const uint32_t*)p_xl,
        (const uint32_t*)p_sgh, (const uint32_t*)p_sgl,
        (float*)p_gate_s, nullptr, nullptr, nullptr, T_TOK, FS, HID);
    tgemm_kernel<0, 1><<<dim3(FS / BN, T_TOK / BM, 1), 256, SMEM_DYN>>>(
        (const uint32_t*)p_xh, (const uint32_t*)p_xl,
        (const uint32_t*)p_suh, (const uint32_t*)p_sul,
        nullptr, (uint32_t*)p_ish, (uint32_t*)p_isl,
        (const float*)p_gate_s, T_TOK, FS, HID);
    tgemm_kernel<0, 0><<<dim3(HID / BN, T_TOK / BM, 1), 256, SMEM_DYN>>>(
        (const uint32_t*)p_ish, (const uint32_t*)p_isl,
        (const uint32_t*)p_sdh, (const uint32_t*)p_sdl,
        out, nullptr, nullptr, nullptr, T_TOK, HID, FS);

    // Routed experts: gate -> (up, silu fused) -> down (atomicAdd into out)
    tgemm_kernel<1, 0><<<dim3(FE / BN, T_TOK / BM, NE), 256, SMEM_DYN>>>(
        (const uint32_t*)p_xh, (const uint32_t*)p_xl,
        (const uint32_t*)p_egh, (const uint32_t*)p_egl,
        (float*)p_gate_r, nullptr, nullptr, nullptr, 0, FE, HID);
    tgemm_kernel<1, 1><<<dim3(FE / BN, T_TOK / BM, NE), 256, SMEM_DYN>>>(
        (const uint32_t*)p_xh, (const uint32_t*)p_xl,
        (const uint32_t*)p_euh, (const uint32_t*)p_eul,
        nullptr, (uint32_t*)p_irh, (uint32_t*)p_irl,
        (const float*)p_gate_r, 0, FE, HID);
    tgemm_kernel<2, 0><<<dim3(HID / BN, T_TOK / BM, NE), 256, SMEM_DYN>>>(
        (const uint32_t*)p_irh, (const uint32_t*)p_irl,
        (const uint32_t*)p_edh, (const uint32_t*)p_edl,
        out, nullptr, nullptr, nullptr, 0, HID, FE);
}

// round 15
// speedup vs baseline: 1.0752x; 1.0752x over previous
#include <cuda_runtime.h>
#include <cuda_fp16.h>
#include <math.h>
#include <stdint.h>

// Problem constants (fixed by the dataset)
#define T_TOK 4096
#define HID   1024
#define NE    16
#define FE    512
#define FS    2048
#define NPAIR (T_TOK * 2)

// ---------------------------------------------------------------------------
// Scratch (all half2-packed words are uint32)
// ---------------------------------------------------------------------------
__device__ float    g_gate_s[(size_t)T_TOK * FS];
__device__ float    g_gate_r[(size_t)NPAIR * FE];
__device__ int      g_cnt[NE];
__device__ int      g_bucket[NE * T_TOK];
__device__ float    g_pw[NPAIR];
// pre-split inputs (hi/lo fp16, half2-packed along K)
__device__ uint32_t g_xh[(size_t)T_TOK * HID / 2];
__device__ uint32_t g_xl[(size_t)T_TOK * HID / 2];
__device__ uint32_t g_sgh[(size_t)HID / 2 * FS],  g_sgl[(size_t)HID / 2 * FS];
__device__ uint32_t g_suh[(size_t)HID / 2 * FS],  g_sul[(size_t)HID / 2 * FS];
__device__ uint32_t g_sdh[(size_t)FS / 2 * HID],  g_sdl[(size_t)FS / 2 * HID];
__device__ uint32_t g_egh[(size_t)NE * HID / 2 * FE], g_egl[(size_t)NE * HID / 2 * FE];
__device__ uint32_t g_euh[(size_t)NE * HID / 2 * FE], g_eul[(size_t)NE * HID / 2 * FE];
__device__ uint32_t g_edh[(size_t)NE * FE / 2 * HID], g_edl[(size_t)NE * FE / 2 * HID];
// pre-split intermediates (written by FUSE epilogues)
__device__ uint32_t g_ish[(size_t)T_TOK * FS / 2],  g_isl[(size_t)T_TOK * FS / 2];
__device__ uint32_t g_irh[(size_t)NPAIR * FE / 2],  g_irl[(size_t)NPAIR * FE / 2];

// ---------------------------------------------------------------------------
// fp16 hi/lo split (validated R10-R14)
// ---------------------------------------------------------------------------
__device__ __forceinline__ void split_h2(float x, float y,
                                         uint32_t& hi, uint32_t& lo) {
    half hx = __float2half_rn(x);
    half hy = __float2half_rn(y);
    half lx = __float2half_rn(x - __half2float(hx));
    half ly = __float2half_rn(y - __half2float(hy));
    __half2 h = __halves2half2(hx, hy);
    __half2 l = __halves2half2(lx, ly);
    hi = *reinterpret_cast<uint32_t*>(&h);
    lo = *reinterpret_cast<uint32_t*>(&l);
}

__device__ __forceinline__ void mma_f16(float* d,
                                        const uint32_t* a,
                                        const uint32_t* b) {
    asm volatile(
        "mma.sync.aligned.m16n8k16.row.col.f32.f16.f16.f32 "
        "{%0,%1,%2,%3}, {%4,%5,%6,%7}, {%8,%9}, {%0,%1,%2,%3};\n"
        : "+f"(d[0]), "+f"(d[1]), "+f"(d[2]), "+f"(d[3])
        : "r"(a[0]), "r"(a[1]), "r"(a[2]), "r"(a[3]),
          "r"(b[0]), "r"(b[1]));
}

#define LDSM_X4(r0, r1, r2, r3, addr) \
    asm volatile("ldmatrix.sync.aligned.m8n8.x4.shared.b16 {%0,%1,%2,%3}, [%4];" \
                 : "=r"(r0), "=r"(r1), "=r"(r2), "=r"(r3) : "r"(addr))

__device__ __forceinline__ void cp_async16(uint32_t dst, const void* src,
                                           int src_bytes) {
    asm volatile("cp.async.cg.shared.global [%0], [%1], 16, %2;\n"
                 :: "r"(dst), "l"(src), "r"(src_bytes) : "memory");
}
#define CP_COMMIT() asm volatile("cp.async.commit_group;" ::: "memory")
#define CP_WAIT2()  asm volatile("cp.async.wait_group 2;" ::: "memory")

__device__ __forceinline__ uint32_t cvta_smem(const void* p) {
    uint32_t a;
    asm("{ .reg .u64 t; cvta.to.shared.u64 t, %1; cvt.u32.u64 %0, t; }"
        : "=r"(a) : "l"(p));
    return a;
}

// ---------------------------------------------------------------------------
// Splitters — 4 words/thread (validated R12/R13; k-major B outputs)
// ---------------------------------------------------------------------------
__global__ void split_contig_kernel(const float* __restrict__ src,
                                    uint32_t* __restrict__ hi,
                                    uint32_t* __restrict__ lo, int nwords) {
    int i = (blockIdx.x * 256 + threadIdx.x) * 4;
    if (i >= nwords) return;
    float2 v0 = ((const float2*)src)[i];
    float2 v1 = ((const float2*)src)[i + 1];
    float2 v2 = ((const float2*)src)[i + 2];
    float2 v3 = ((const float2*)src)[i + 3];
    uint4 h, l;
    split_h2(v0.x, v0.y, h.x, l.x);
    split_h2(v1.x, v1.y, h.y, l.y);
    split_h2(v2.x, v2.y, h.z, l.z);
    split_h2(v3.x, v3.y, h.w, l.w);
    *(uint4*)(hi + i) = h;
    *(uint4*)(lo + i) = l;
}
__global__ void split_strided_kernel(const float* __restrict__ src,
                                     uint32_t* __restrict__ hi,
                                     uint32_t* __restrict__ lo,
                                     int nwords, int N) {
    int i = (blockIdx.x * 256 + threadIdx.x) * 4;
    if (i >= nwords) return;
    int kp = i / N, n = i - kp * N;
    float4 a = *(const float4*)(src + (size_t)(2 * kp) * N + n);
    float4 b = *(const float4*)(src + (size_t)(2 * kp + 1) * N + n);
    uint4 h, l;
    split_h2(a.x, b.x, h.x, l.x);
    split_h2(a.y, b.y, h.y, l.y);
    split_h2(a.z, b.z, h.z, l.z);
    split_h2(a.w, b.w, h.w, l.w);
    *(uint4*)(hi + i) = h;
    *(uint4*)(lo + i) = l;
}

// ---------------------------------------------------------------------------
// Router (validated rounds 1-14)
// ---------------------------------------------------------------------------
__global__ void zero_counts_kernel() {
    if (threadIdx.x < NE) g_cnt[threadIdx.x] = 0;
}

__global__ void router_kernel(const float* __restrict__ x,
                              const float* __restrict__ rw) {
    int warp = threadIdx.x >> 5;
    int lane = threadIdx.x & 31;
    int t = blockIdx.x * (blockDim.x >> 5) + warp;
    if (t >= T_TOK) return;

    float acc[NE];
#pragma unroll
    for (int e = 0; e < NE; e++) acc[e] = 0.0f;

    const float* xr = x + (size_t)t * HID;
    for (int d = lane; d < HID; d += 32) {
        float xv = xr[d];
        const float* r = rw + (size_t)d * NE;
#pragma unroll
        for (int e = 0; e < NE; e++) acc[e] = fmaf(xv, r[e], acc[e]);
    }
#pragma unroll
    for (int e = 0; e < NE; e++) {
#pragma unroll
        for (int off = 16; off; off >>= 1)
            acc[e] += __shfl_xor_sync(0xffffffffu, acc[e], off);
    }

    if (lane == 0) {
        float mx = acc[0];
#pragma unroll
        for (int e = 1; e < NE; e++) mx = fmaxf(mx, acc[e]);
        float p[NE];
        float s = 0.0f;
#pragma unroll
        for (int e = 0; e < NE; e++) { p[e] = expf(acc[e] - mx); s += p[e]; }
        float inv = 1.0f / s;
#pragma unroll
        for (int e = 0; e < NE; e++) p[e] *= inv;

        int   i0 = 0; float w0 = p[0];
#pragma unroll
        for (int e = 1; e < NE; e++) if (p[e] > w0) { w0 = p[e]; i0 = e; }
        int   i1 = -1; float w1 = -1.0f;
#pragma unroll
        for (int e = 0; e < NE; e++)
            if (e != i0 && p[e] > w1) { w1 = p[e]; i1 = e; }

        int pos0 = atomicAdd(&g_cnt[i0], 1);
        g_bucket[i0 * T_TOK + pos0] = 2 * t;
        int pos1 = atomicAdd(&g_cnt[i1], 1);
        g_bucket[i1 * T_TOK + pos1] = 2 * t + 1;
        g_pw[2 * t]     = w0;
        g_pw[2 * t + 1] = w1;
    }
}

// ---------------------------------------------------------------------------
// Tensor GEMM 128x128x16, 256 threads, pre-split fp16, cp.async 4-stage,
// m16n8k16 HMMA, A frags via ldmatrix.x4 (R13 structure, 979us validated).
// CHANGE vs R13: A producer = 1 thread per (row, hi/lo) -> store phases tile
// banks exactly ({0,12,24,4,16,28,8,20} mod 32), removing the 2-way A-store
// conflict. Gmem coalescing unchanged (same contiguous row chunks).
// B gmem stays k-major [K/2][N] (coalesced loads — the R14 lesson).
// MODE 0: plain. MODE 1: gather x rows by pair>>1, scatter C by pair.
// MODE 2: gather rows by pair, scale by router weight, atomicAdd into C[token].
// FUSE 1: write CH/CL = split(silu(G) * acc) instead of C.
// ---------------------------------------------------------------------------
#define BM 128
#define BN 128
#define BK 16
#define A_PAD 12
#define B_PAD 136
#define OFF_AL 1536
#define OFF_BH 3072
#define OFF_BL 4160
#define STAGEF 5248
#define NSTG 4
#define SMEM_DYN (NSTG * STAGEF * 4)

template <int MODE, int FUSE>
__global__ __launch_bounds__(256, 2)
void tgemm_kernel(const uint32_t* __restrict__ Ahg,
                  const uint32_t* __restrict__ Alg,
                  const uint32_t* __restrict__ Bhg,
                  const uint32_t* __restrict__ Blg,
                  float* __restrict__ C,
                  uint32_t* __restrict__ CH,
                  uint32_t* __restrict__ CL,
                  const float* __restrict__ G,
                  int M, int N, int K) {
    const int e = blockIdx.z;
    int m_rows = M;
    const int* rowlist = nullptr;
    if (MODE != 0) {
        m_rows  = g_cnt[e];
        rowlist = g_bucket + e * T_TOK;
        Bhg += (size_t)e * (K / 2) * N;
        Blg += (size_t)e * (K / 2) * N;
    }
    const int m0 = blockIdx.y * BM;
    const int n0 = blockIdx.x * BN;
    if (m0 >= m_rows) return;

    extern __shared__ uint32_t sm[];
    const uint32_t smem_base = cvta_smem(sm);

    const int tid  = threadIdx.x;
    const int lane = tid & 31;
    const int wid  = tid >> 5;
    const int warp_m = wid >> 2;
    const int warp_n = wid & 3;
    const int g  = lane >> 2;
    const int t4 = lane & 3;
    const int mb = warp_m * 64;
    const int nb = warp_n * 32;

    const int KW = K / 2;

    // --- A producer: 1 thread per (row, hi/lo) — conflict-free stores ---
    const int prow = tid & 127;
    const int phl  = tid >> 7;       // 0 = hi, 1 = lo
    // --- B producer: unchanged from R13 (k-major, coalesced) ---
    const int bkp  = tid >> 5;
    const int bc4  = (tid & 31) * 4;

    const int  ar_g = m0 + prow;
    const bool av   = ar_g < m_rows;
    const int  aidx = av ? ar_g : 0;
    int rowidx;
    if (MODE == 0)      rowidx = aidx;
    else if (MODE == 1) rowidx = rowlist[aidx] >> 1;
    else                rowidx = rowlist[aidx];
    const uint32_t* Asrc = (phl ? Alg : Ahg) + (size_t)rowidx * KW;
    const uint32_t* BgH  = Bhg + (size_t)bkp * N + n0 + bc4;
    const uint32_t* BgL  = Blg + (size_t)bkp * N + n0 + bc4;
    const int abytes = av ? 16 : 0;

    const uint32_t a_dst = smem_base + (phl * OFF_AL + prow * A_PAD) * 4;
    const uint32_t b_dst = smem_base + (bkp * B_PAD + bc4) * 4;
    const int KT = K / BK;

    auto issue_stage = [&](int kt) {
        const uint32_t so = (uint32_t)((kt % NSTG) * (STAGEF * 4));
        const int kw0 = kt * 8;
        cp_async16(a_dst + so,      Asrc + kw0,     abytes);
        cp_async16(a_dst + so + 16, Asrc + kw0 + 4, abytes);
        cp_async16(b_dst + so + OFF_BH * 4, BgH + (size_t)kw0 * N, 16);
        cp_async16(b_dst + so + OFF_BL * 4, BgL + (size_t)kw0 * N, 16);
    };

    // ldmatrix per-lane source address within the A tile of a stage
    const int sel = lane >> 3;
    const int rr  = lane & 7;
    const uint32_t a_lm_base =
        (uint32_t)(((mb + rr + ((sel & 1) << 3)) * A_PAD + ((sel >> 1) << 2)) * 4);

    issue_stage(0); CP_COMMIT();
    issue_stage(1); CP_COMMIT();
    issue_stage(2); CP_COMMIT();

    float acc[4][4][4];
#pragma unroll
    for (int i = 0; i < 4; i++)
#pragma unroll
        for (int j = 0; j < 4; j++)
#pragma unroll
            for (int r = 0; r < 4; r++) acc[i][j][r] = 0.0f;

    for (int kt = 0; kt < KT; kt++) {
        CP_WAIT2();
        __syncthreads();
        if (kt + 3 < KT) issue_stage(kt + 3);
        CP_COMMIT();

        const uint32_t stage_b = smem_base + (uint32_t)((kt % NSTG) * (STAGEF * 4));
        const uint32_t* Bh = sm + (kt % NSTG) * STAGEF + OFF_BH;
        const uint32_t* Bl = Bh + (OFF_BL - OFF_BH);

        uint32_t bh[4][2], bl[4][2];
#pragma unroll
        for (int nt = 0; nt < 4; nt++) {
            const int col = nb + nt * 8 + g;
            bh[nt][0] = Bh[t4 * B_PAD + col];
            bh[nt][1] = Bh[(t4 + 4) * B_PAD + col];
            bl[nt][0] = Bl[t4 * B_PAD + col];
            bl[nt][1] = Bl[(t4 + 4) * B_PAD + col];
        }
#pragma unroll
        for (int mt = 0; mt < 4; mt++) {
            const uint32_t a_addr = stage_b + a_lm_base
                                  + (uint32_t)(mt * 16 * A_PAD * 4);
            uint32_t ah[4], al[4];
            LDSM_X4(ah[0], ah[1], ah[2], ah[3], a_addr);
            LDSM_X4(al[0], al[1], al[2], al[3], a_addr + OFF_AL * 4);
#pragma unroll
            for (int nt = 0; nt < 4; nt++) mma_f16(acc[mt][nt], ah, bh[nt]);
#pragma unroll
            for (int nt = 0; nt < 4; nt++) mma_f16(acc[mt][nt], ah, bl[nt]);
#pragma unroll
            for (int nt = 0; nt < 4; nt++) mma_f16(acc[mt][nt], al, bh[nt]);
        }
    }

    // Epilogue (validated R12/R13)
#pragma unroll
    for (int mt = 0; mt < 4; mt++) {
        const int r0 = m0 + mb + mt * 16 + g;
        const int r1 = r0 + 8;
        size_t ro0 = 0, ro1 = 0;
        bool v0 = r0 < m_rows, v1 = r1 < m_rows;
        float s0 = 1.0f, s1 = 1.0f;
        if (v0) {
            if (MODE == 0) ro0 = (size_t)r0 * N;
            else {
                const int p = rowlist[r0];
                if (MODE == 2) { s0 = g_pw[p]; ro0 = (size_t)(p >> 1) * N; }
                else ro0 = (size_t)p * N;
            }
        }
        if (v1) {
            if (MODE == 0) ro1 = (size_t)r1 * N;
            else {
                const int p = rowlist[r1];
                if (MODE == 2) { s1 = g_pw[p]; ro1 = (size_t)(p >> 1) * N; }
                else ro1 = (size_t)p * N;
            }
        }
#pragma unroll
        for (int nt = 0; nt < 4; nt++) {
            const int c = n0 + nb + nt * 8 + 2 * t4;
            if (v0) {
                float o0 = acc[mt][nt][0] * s0, o1 = acc[mt][nt][1] * s0;
                if (FUSE) {
                    float2 gv = *(const float2*)(G + ro0 + c);
                    o0 *= gv.x / (1.0f + expf(-gv.x));
                    o1 *= gv.y / (1.0f + expf(-gv.y));
                    uint32_t h, l;
                    split_h2(o0, o1, h, l);
                    const size_t wi = (ro0 + c) >> 1;
                    CH[wi] = h; CL[wi] = l;
                } else if (MODE == 2) {
                    atomicAdd(C + ro0 + c, o0);
                    atomicAdd(C + ro0 + c + 1, o1);
                } else {
                    *(float2*)(C + ro0 + c) = make_float2(o0, o1);
                }
            }
            if (v1) {
                float o0 = acc[mt][nt][2] * s1, o1 = acc[mt][nt][3] * s1;
                if (FUSE) {
                    float2 gv = *(const float2*)(G + ro1 + c);
                    o0 *= gv.x / (1.0f + expf(-gv.x));
                    o1 *= gv.y / (1.0f + expf(-gv.y));
                    uint32_t h, l;
                    split_h2(o0, o1, h, l);
                    const size_t wi = (ro1 + c) >> 1;
                    CH[wi] = h; CL[wi] = l;
                } else if (MODE == 2) {
                    atomicAdd(C + ro1 + c, o0);
                    atomicAdd(C + ro1 + c + 1, o1);
                } else {
                    *(float2*)(C + ro1 + c) = make_float2(o0, o1);
                }
            }
        }
    }
}

// ---------------------------------------------------------------------------
// Launch
// ---------------------------------------------------------------------------
extern "C" void kernel_launch(void* const* d_in, const int* in_sizes, int n_in,
                              void* d_out, int out_size) {
    const float* x  = (const float*)d_in[0];
    const float* rw = (const float*)d_in[1];
    const float* eg = (const float*)d_in[2];
    const float* eu = (const float*)d_in[3];
    const float* ed = (const float*)d_in[4];
    const float* sg = (const float*)d_in[5];
    const float* su = (const float*)d_in[6];
    const float* sd = (const float*)d_in[7];
    float* out = (float*)d_out;

#define SYM(p, s) void* p; cudaGetSymbolAddress(&p, s)
    SYM(p_gate_s, g_gate_s); SYM(p_gate_r, g_gate_r);
    SYM(p_xh, g_xh);   SYM(p_xl, g_xl);
    SYM(p_sgh, g_sgh); SYM(p_sgl, g_sgl);
    SYM(p_suh, g_suh); SYM(p_sul, g_sul);
    SYM(p_sdh, g_sdh); SYM(p_sdl, g_sdl);
    SYM(p_egh, g_egh); SYM(p_egl, g_egl);
    SYM(p_euh, g_euh); SYM(p_eul, g_eul);
    SYM(p_edh, g_edh); SYM(p_edl, g_edl);
    SYM(p_ish, g_ish); SYM(p_isl, g_isl);
    SYM(p_irh, g_irh); SYM(p_irl, g_irl);
#undef SYM

    cudaFuncSetAttribute(tgemm_kernel<0, 0>,
                         cudaFuncAttributeMaxDynamicSharedMemorySize, SMEM_DYN);
    cudaFuncSetAttribute(tgemm_kernel<0, 1>,
                         cudaFuncAttributeMaxDynamicSharedMemorySize, SMEM_DYN);
    cudaFuncSetAttribute(tgemm_kernel<1, 0>,
                         cudaFuncAttributeMaxDynamicSharedMemorySize, SMEM_DYN);
    cudaFuncSetAttribute(tgemm_kernel<1, 1>,
                         cudaFuncAttributeMaxDynamicSharedMemorySize, SMEM_DYN);
    cudaFuncSetAttribute(tgemm_kernel<2, 0>,
                         cudaFuncAttributeMaxDynamicSharedMemorySize, SMEM_DYN);

    zero_counts_kernel<<<1, 32>>>();
    router_kernel<<<T_TOK / 4, 128>>>(x, rw);

    split_contig_kernel<<<(T_TOK * HID / 2 / 4) / 256, 256>>>(
        x, (uint32_t*)p_xh, (uint32_t*)p_xl, T_TOK * HID / 2);
    split_strided_kernel<<<(HID / 2 * FS / 4) / 256, 256>>>(
        sg, (uint32_t*)p_sgh, (uint32_t*)p_sgl, HID / 2 * FS, FS);
    split_strided_kernel<<<(HID / 2 * FS / 4) / 256, 256>>>(
        su, (uint32_t*)p_suh, (uint32_t*)p_sul, HID / 2 * FS, FS);
    split_strided_kernel<<<(FS / 2 * HID / 4) / 256, 256>>>(
        sd, (uint32_t*)p_sdh, (uint32_t*)p_sdl, FS / 2 * HID, HID);
    split_strided_kernel<<<(NE * HID / 2 * FE / 4) / 256, 256>>>(
        eg, (uint32_t*)p_egh, (uint32_t*)p_egl, NE * HID / 2 * FE, FE);
    split_strided_kernel<<<(NE * HID / 2 * FE / 4) / 256, 256>>>(
        eu, (uint32_t*)p_euh, (uint32_t*)p_eul, NE * HID / 2 * FE, FE);
    split_strided_kernel<<<(NE * FE / 2 * HID / 4) / 256, 256>>>(
        ed, (uint32_t*)p_edh, (uint32_t*)p_edl, NE * FE / 2 * HID, HID);

    // Shared expert: gate -> (up, silu fused, split-write) -> down (writes out)
    tgemm_kernel<0, 0><<<dim3(FS / BN, T_TOK / BM, 1), 256, SMEM_DYN>>>(
        (const uint32_t*)p_xh, (const uint32_t*)p_xl,
        (const uint32_t*)p_sgh, (const uint32_t*)p_sgl,
        (float*)p_gate_s, nullptr, nullptr, nullptr, T_TOK, FS, HID);
    tgemm_kernel<0, 1><<<dim3(FS / BN, T_TOK / BM, 1), 256, SMEM_DYN>>>(
        (const uint32_t*)p_xh, (const uint32_t*)p_xl,
        (const uint32_t*)p_suh, (const uint32_t*)p_sul,
        nullptr, (uint32_t*)p_ish, (uint32_t*)p_isl,
        (const float*)p_gate_s, T_TOK, FS, HID);
    tgemm_kernel<0, 0><<<dim3(HID / BN, T_TOK / BM, 1), 256, SMEM_DYN>>>(
        (const uint32_t*)p_ish, (const uint32_t*)p_isl,
        (const uint32_t*)p_sdh, (const uint32_t*)p_sdl,
        out, nullptr, nullptr, nullptr, T_TOK, HID, FS);

    // Routed experts: gate -> (up, silu fused) -> down (atomicAdd into out)
    tgemm_kernel<1, 0><<<dim3(FE / BN, T_TOK / BM, NE), 256, SMEM_DYN>>>(
        (const uint32_t*)p_xh, (const uint32_t*)p_xl,
        (const uint32_t*)p_egh, (const uint32_t*)p_egl,
        (float*)p_gate_r, nullptr, nullptr, nullptr, 0, FE, HID);
    tgemm_kernel<1, 1><<<dim3(FE / BN, T_TOK / BM, NE), 256, SMEM_DYN>>>(
        (const uint32_t*)p_xh, (const uint32_t*)p_xl,
        (const uint32_t*)p_euh, (const uint32_t*)p_eul,
        nullptr, (uint32_t*)p_irh, (uint32_t*)p_irl,
        (const float*)p_gate_r, 0, FE, HID);
    tgemm_kernel<2, 0><<<dim3(HID / BN, T_TOK / BM, NE), 256, SMEM_DYN>>>(
        (const uint32_t*)p_irh, (const uint32_t*)p_irl,
        (const uint32_t*)p_edh, (const uint32_t*)p_edl,
        out, nullptr, nullptr, nullptr, 0, HID, FE);
}

// round 16
// speedup vs baseline: 1.1647x; 1.0832x over previous
#include <cuda_runtime.h>
#include <cuda_fp16.h>
#include <math.h>
#include <stdint.h>

// Problem constants (fixed by the dataset)
#define T_TOK 4096
#define HID   1024
#define NE    16
#define FE    512
#define FS    2048
#define NPAIR (T_TOK * 2)

// ---------------------------------------------------------------------------
// Scratch (all half2-packed words are uint32)
// ---------------------------------------------------------------------------
__device__ float    g_gate_s[(size_t)T_TOK * FS];
__device__ float    g_gate_r[(size_t)NPAIR * FE];
__device__ int      g_cnt[NE];
__device__ int      g_bucket[NE * T_TOK];
__device__ float    g_pw[NPAIR];
// pre-split A-side (rows x K/2 words, k-pair packed: word i = (k2i, k2i+1))
__device__ uint32_t g_xh[(size_t)T_TOK * HID / 2];
__device__ uint32_t g_xl[(size_t)T_TOK * HID / 2];
// pre-split B-side, FRAGMENT-PAIR-MAJOR: [K/16][4][N][2] words
//   word(kt,r,n,s) = half2 for kp = 8kt + r + 4s  (k = 2kp, 2kp+1)
__device__ uint32_t g_sgh[(size_t)HID / 2 * FS],  g_sgl[(size_t)HID / 2 * FS];
__device__ uint32_t g_suh[(size_t)HID / 2 * FS],  g_sul[(size_t)HID / 2 * FS];
__device__ uint32_t g_sdh[(size_t)FS / 2 * HID],  g_sdl[(size_t)FS / 2 * HID];
__device__ uint32_t g_egh[(size_t)NE * HID / 2 * FE], g_egl[(size_t)NE * HID / 2 * FE];
__device__ uint32_t g_euh[(size_t)NE * HID / 2 * FE], g_eul[(size_t)NE * HID / 2 * FE];
__device__ uint32_t g_edh[(size_t)NE * FE / 2 * HID], g_edl[(size_t)NE * FE / 2 * HID];
// pre-split intermediates (A-side packing, written by FUSE epilogues)
__device__ uint32_t g_ish[(size_t)T_TOK * FS / 2],  g_isl[(size_t)T_TOK * FS / 2];
__device__ uint32_t g_irh[(size_t)NPAIR * FE / 2],  g_irl[(size_t)NPAIR * FE / 2];

// ---------------------------------------------------------------------------
// fp16 hi/lo split (validated R10-R15)
// ---------------------------------------------------------------------------
__device__ __forceinline__ void split_h2(float x, float y,
                                         uint32_t& hi, uint32_t& lo) {
    half hx = __float2half_rn(x);
    half hy = __float2half_rn(y);
    half lx = __float2half_rn(x - __half2float(hx));
    half ly = __float2half_rn(y - __half2float(hy));
    __half2 h = __halves2half2(hx, hy);
    __half2 l = __halves2half2(lx, ly);
    hi = *reinterpret_cast<uint32_t*>(&h);
    lo = *reinterpret_cast<uint32_t*>(&l);
}

__device__ __forceinline__ void mma_f16(float* d,
                                        const uint32_t* a,
                                        const uint32_t* b) {
    asm volatile(
        "mma.sync.aligned.m16n8k16.row.col.f32.f16.f16.f32 "
        "{%0,%1,%2,%3}, {%4,%5,%6,%7}, {%8,%9}, {%0,%1,%2,%3};\n"
        : "+f"(d[0]), "+f"(d[1]), "+f"(d[2]), "+f"(d[3])
        : "r"(a[0]), "r"(a[1]), "r"(a[2]), "r"(a[3]),
          "r"(b[0]), "r"(b[1]));
}

#define LDSM_X4(r0, r1, r2, r3, addr) \
    asm volatile("ldmatrix.sync.aligned.m8n8.x4.shared.b16 {%0,%1,%2,%3}, [%4];" \
                 : "=r"(r0), "=r"(r1), "=r"(r2), "=r"(r3) : "r"(addr))

__device__ __forceinline__ void cp_async16(uint32_t dst, const void* src,
                                           int src_bytes) {
    asm volatile("cp.async.cg.shared.global [%0], [%1], 16, %2;\n"
                 :: "r"(dst), "l"(src), "r"(src_bytes) : "memory");
}
#define CP_COMMIT() asm volatile("cp.async.commit_group;" ::: "memory")
#define CP_WAIT2()  asm volatile("cp.async.wait_group 2;" ::: "memory")

__device__ __forceinline__ uint32_t cvta_smem(const void* p) {
    uint32_t a;
    asm("{ .reg .u64 t; cvta.to.shared.u64 t, %1; cvt.u32.u64 %0, t; }"
        : "=r"(a) : "l"(p));
    return a;
}

// ---------------------------------------------------------------------------
// Splitters
// ---------------------------------------------------------------------------
// A-side: pairs along contiguous dim (validated R12-R15)
__global__ void split_contig_kernel(const float* __restrict__ src,
                                    uint32_t* __restrict__ hi,
                                    uint32_t* __restrict__ lo, int nwords) {
    int i = (blockIdx.x * 256 + threadIdx.x) * 4;
    if (i >= nwords) return;
    float2 v0 = ((const float2*)src)[i];
    float2 v1 = ((const float2*)src)[i + 1];
    float2 v2 = ((const float2*)src)[i + 2];
    float2 v3 = ((const float2*)src)[i + 3];
    uint4 h, l;
    split_h2(v0.x, v0.y, h.x, l.x);
    split_h2(v1.x, v1.y, h.y, l.y);
    split_h2(v2.x, v2.y, h.z, l.z);
    split_h2(v3.x, v3.y, h.w, l.w);
    *(uint4*)(hi + i) = h;
    *(uint4*)(lo + i) = l;
}
// B-side: fragment-pair-major. src [K][N] row-major (expert via blockIdx.z).
// out word index = ((kt*4 + r)*N + n)*2 + s, value = half2(src[k][n], src[k+1][n]),
// k = 2*(8*kt + r + 4*s). Thread covers (kt, r, npair): 2 cols x 2 slots = 4 words
// -> one 16B write to hi and one to lo. Reads: 4x float2, coalesced across np.
__global__ void split_bpair_kernel(const float* __restrict__ src,
                                   uint32_t* __restrict__ hi,
                                   uint32_t* __restrict__ lo,
                                   int N, int K) {
    src += (size_t)blockIdx.z * K * N;
    hi  += (size_t)blockIdx.z * (size_t)(K / 2) * N;
    lo  += (size_t)blockIdx.z * (size_t)(K / 2) * N;
    const int nhalf = N >> 1;
    int idx = blockIdx.x * 256 + threadIdx.x;
    if (idx >= (K / 16) * 4 * nhalf) return;
    const int np  = idx % nhalf;
    const int rem = idx / nhalf;
    const int r   = rem & 3;
    const int kt  = rem >> 2;
    const int n   = 2 * np;
    const int k0  = 2 * (8 * kt + r);       // slot 0
    const int k1  = 2 * (8 * kt + r + 4);   // slot 1
    float2 a0 = *(const float2*)(src + (size_t)k0 * N + n);
    float2 a1 = *(const float2*)(src + (size_t)(k0 + 1) * N + n);
    float2 b0 = *(const float2*)(src + (size_t)k1 * N + n);
    float2 b1 = *(const float2*)(src + (size_t)(k1 + 1) * N + n);
    uint4 h, l;
    split_h2(a0.x, a1.x, h.x, l.x);   // (n,   s=0)
    split_h2(b0.x, b1.x, h.y, l.y);   // (n,   s=1)
    split_h2(a0.y, a1.y, h.z, l.z);   // (n+1, s=0)
    split_h2(b0.y, b1.y, h.w, l.w);   // (n+1, s=1)
    const size_t o = ((size_t)(kt * 4 + r) * N + n) * 2;
    *(uint4*)(hi + o) = h;
    *(uint4*)(lo + o) = l;
}

// ---------------------------------------------------------------------------
// Router (validated rounds 1-15)
// ---------------------------------------------------------------------------
__global__ void zero_counts_kernel() {
    if (threadIdx.x < NE) g_cnt[threadIdx.x] = 0;
}

__global__ void router_kernel(const float* __restrict__ x,
                              const float* __restrict__ rw) {
    int warp = threadIdx.x >> 5;
    int lane = threadIdx.x & 31;
    int t = blockIdx.x * (blockDim.x >> 5) + warp;
    if (t >= T_TOK) return;

    float acc[NE];
#pragma unroll
    for (int e = 0; e < NE; e++) acc[e] = 0.0f;

    const float* xr = x + (size_t)t * HID;
    for (int d = lane; d < HID; d += 32) {
        float xv = xr[d];
        const float* r = rw + (size_t)d * NE;
#pragma unroll
        for (int e = 0; e < NE; e++) acc[e] = fmaf(xv, r[e], acc[e]);
    }
#pragma unroll
    for (int e = 0; e < NE; e++) {
#pragma unroll
        for (int off = 16; off; off >>= 1)
            acc[e] += __shfl_xor_sync(0xffffffffu, acc[e], off);
    }

    if (lane == 0) {
        float mx = acc[0];
#pragma unroll
        for (int e = 1; e < NE; e++) mx = fmaxf(mx, acc[e]);
        float p[NE];
        float s = 0.0f;
#pragma unroll
        for (int e = 0; e < NE; e++) { p[e] = expf(acc[e] - mx); s += p[e]; }
        float inv = 1.0f / s;
#pragma unroll
        for (int e = 0; e < NE; e++) p[e] *= inv;

        int   i0 = 0; float w0 = p[0];
#pragma unroll
        for (int e = 1; e < NE; e++) if (p[e] > w0) { w0 = p[e]; i0 = e; }
        int   i1 = -1; float w1 = -1.0f;
#pragma unroll
        for (int e = 0; e < NE; e++)
            if (e != i0 && p[e] > w1) { w1 = p[e]; i1 = e; }

        int pos0 = atomicAdd(&g_cnt[i0], 1);
        g_bucket[i0 * T_TOK + pos0] = 2 * t;
        int pos1 = atomicAdd(&g_cnt[i1], 1);
        g_bucket[i1 * T_TOK + pos1] = 2 * t + 1;
        g_pw[2 * t]     = w0;
        g_pw[2 * t + 1] = w1;
    }
}

// ---------------------------------------------------------------------------
// Tensor GEMM 128x128x16, 256 threads, pre-split fp16, cp.async 4-stage,
// m16n8k16 HMMA, A frags via ldmatrix.x4 — R13 structure (979us validated).
// CHANGE vs R13: B in fragment-pair-major layout -> B frag loads are uint2
// (8 LDS.64 replace 16 LDS.32 per warp-ktile). Gmem coalescing identical
// (contiguous 16B per thread, consecutive threads adjacent). Smem B [4][264]:
// store phases 4*(tid&63) mod 32 and load phases t4*8+2g both tile all banks.
// MODE 0: plain. MODE 1: gather x rows by pair>>1, scatter C by pair.
// MODE 2: gather rows by pair, scale by router weight, atomicAdd into C[token].
// FUSE 1: write CH/CL = split(silu(G) * acc) instead of C.
// ---------------------------------------------------------------------------
#define BM 128
#define BN 128
#define BK 16
#define A_PAD 12
#define B_ROW 264
#define OFF_AL 1536
#define OFF_BH 3072
#define OFF_BL 4128
#define STAGEF 5184
#define NSTG 4
#define SMEM_DYN (NSTG * STAGEF * 4)

template <int MODE, int FUSE>
__global__ __launch_bounds__(256, 2)
void tgemm_kernel(const uint32_t* __restrict__ Ahg,
                  const uint32_t* __restrict__ Alg,
                  const uint32_t* __restrict__ Bhg,
                  const uint32_t* __restrict__ Blg,
                  float* __restrict__ C,
                  uint32_t* __restrict__ CH,
                  uint32_t* __restrict__ CL,
                  const float* __restrict__ G,
                  int M, int N, int K) {
    const int e = blockIdx.z;
    int m_rows = M;
    const int* rowlist = nullptr;
    if (MODE != 0) {
        m_rows  = g_cnt[e];
        rowlist = g_bucket + e * T_TOK;
        Bhg += (size_t)e * (K / 2) * N;
        Blg += (size_t)e * (K / 2) * N;
    }
    const int m0 = blockIdx.y * BM;
    const int n0 = blockIdx.x * BN;
    if (m0 >= m_rows) return;

    extern __shared__ uint32_t sm[];
    const uint32_t smem_base = cvta_smem(sm);

    const int tid  = threadIdx.x;
    const int lane = tid & 31;
    const int wid  = tid >> 5;
    const int warp_m = wid >> 2;
    const int warp_n = wid & 3;
    const int g  = lane >> 2;
    const int t4 = lane & 3;
    const int mb = warp_m * 64;
    const int nb = warp_n * 32;

    const int KW = K / 2;

    // --- A producer (R13 mapping — validated 979us) ---
    const int am  = tid >> 1;
    const int akq = (tid & 1) * 4;           // word offset (4 words = 16B)
    // --- B producer: fragment-pair-major ---
    const int br  = tid >> 6;                // 0..3
    const int bc  = (tid & 63) * 2;          // column (pairs of cols per thread)

    const int  ar_g = m0 + am;
    const bool av   = ar_g < m_rows;
    const int  aidx = av ? ar_g : 0;
    int rowidx;
    if (MODE == 0)      rowidx = aidx;
    else if (MODE == 1) rowidx = rowlist[aidx] >> 1;
    else                rowidx = rowlist[aidx];
    const uint32_t* ArH = Ahg + (size_t)rowidx * KW + akq;
    const uint32_t* ArL = Alg + (size_t)rowidx * KW + akq;
    const uint32_t* BgH = Bhg + ((size_t)br * N + n0 + bc) * 2;
    const uint32_t* BgL = Blg + ((size_t)br * N + n0 + bc) * 2;
    const int abytes = av ? 16 : 0;

    const uint32_t a_dst = smem_base + (am * A_PAD + akq) * 4;
    const uint32_t b_dst = smem_base + (OFF_BH + br * B_ROW + bc * 2) * 4;
    const int KT = K / BK;
    const size_t b_kt_stride = (size_t)8 * N;   // words per ktile in B gmem

    auto issue_stage = [&](int kt) {
        const uint32_t so = (uint32_t)((kt % NSTG) * (STAGEF * 4));
        const int kw0 = kt * 8;
        cp_async16(a_dst + so,              ArH + kw0, abytes);
        cp_async16(a_dst + so + OFF_AL * 4, ArL + kw0, abytes);
        cp_async16(b_dst + so,                          BgH + (size_t)kt * b_kt_stride, 16);
        cp_async16(b_dst + so + (OFF_BL - OFF_BH) * 4,  BgL + (size_t)kt * b_kt_stride, 16);
    };

    // ldmatrix per-lane source address within the A tile of a stage
    const int sel = lane >> 3;
    const int rr  = lane & 7;
    const uint32_t a_lm_base =
        (uint32_t)(((mb + rr + ((sel & 1) << 3)) * A_PAD + ((sel >> 1) << 2)) * 4);

    issue_stage(0); CP_COMMIT();
    issue_stage(1); CP_COMMIT();
    issue_stage(2); CP_COMMIT();

    float acc[4][4][4];
#pragma unroll
    for (int i = 0; i < 4; i++)
#pragma unroll
        for (int j = 0; j < 4; j++)
#pragma unroll
            for (int r = 0; r < 4; r++) acc[i][j][r] = 0.0f;

    for (int kt = 0; kt < KT; kt++) {
        CP_WAIT2();
        __syncthreads();
        if (kt + 3 < KT) issue_stage(kt + 3);
        CP_COMMIT();

        const uint32_t stage_b = smem_base + (uint32_t)((kt % NSTG) * (STAGEF * 4));
        const uint32_t* Bh = sm + (kt % NSTG) * STAGEF + OFF_BH;
        const uint32_t* Bl = Bh + (OFF_BL - OFF_BH);

        uint32_t bh[4][2], bl[4][2];
#pragma unroll
        for (int nt = 0; nt < 4; nt++) {
            const int col = nb + nt * 8 + g;
            uint2 hv = *(const uint2*)&Bh[t4 * B_ROW + col * 2];
            uint2 lv = *(const uint2*)&Bl[t4 * B_ROW + col * 2];
            bh[nt][0] = hv.x; bh[nt][1] = hv.y;
            bl[nt][0] = lv.x; bl[nt][1] = lv.y;
        }
#pragma unroll
        for (int mt = 0; mt < 4; mt++) {
            const uint32_t a_addr = stage_b + a_lm_base
                                  + (uint32_t)(mt * 16 * A_PAD * 4);
            uint32_t ah[4], al[4];
            LDSM_X4(ah[0], ah[1], ah[2], ah[3], a_addr);
            LDSM_X4(al[0], al[1], al[2], al[3], a_addr + OFF_AL * 4);
#pragma unroll
            for (int nt = 0; nt < 4; nt++) mma_f16(acc[mt][nt], ah, bh[nt]);
#pragma unroll
            for (int nt = 0; nt < 4; nt++) mma_f16(acc[mt][nt], ah, bl[nt]);
#pragma unroll
            for (int nt = 0; nt < 4; nt++) mma_f16(acc[mt][nt], al, bh[nt]);
        }
    }

    // Epilogue (validated R12/R13)
#pragma unroll
    for (int mt = 0; mt < 4; mt++) {
        const int r0 = m0 + mb + mt * 16 + g;
        const int r1 = r0 + 8;
        size_t ro0 = 0, ro1 = 0;
        bool v0 = r0 < m_rows, v1 = r1 < m_rows;
        float s0 = 1.0f, s1 = 1.0f;
        if (v0) {
            if (MODE == 0) ro0 = (size_t)r0 * N;
            else {
                const int p = rowlist[r0];
                if (MODE == 2) { s0 = g_pw[p]; ro0 = (size_t)(p >> 1) * N; }
                else ro0 = (size_t)p * N;
            }
        }
        if (v1) {
            if (MODE == 0) ro1 = (size_t)r1 * N;
            else {
                const int p = rowlist[r1];
                if (MODE == 2) { s1 = g_pw[p]; ro1 = (size_t)(p >> 1) * N; }
                else ro1 = (size_t)p * N;
            }
        }
#pragma unroll
        for (int nt = 0; nt < 4; nt++) {
            const int c = n0 + nb + nt * 8 + 2 * t4;
            if (v0) {
                float o0 = acc[mt][nt][0] * s0, o1 = acc[mt][nt][1] * s0;
                if (FUSE) {
                    float2 gv = *(const float2*)(G + ro0 + c);
                    o0 *= gv.x / (1.0f + expf(-gv.x));
                    o1 *= gv.y / (1.0f + expf(-gv.y));
                    uint32_t h, l;
                    split_h2(o0, o1, h, l);
                    const size_t wi = (ro0 + c) >> 1;
                    CH[wi] = h; CL[wi] = l;
                } else if (MODE == 2) {
                    atomicAdd(C + ro0 + c, o0);
                    atomicAdd(C + ro0 + c + 1, o1);
                } else {
                    *(float2*)(C + ro0 + c) = make_float2(o0, o1);
                }
            }
            if (v1) {
                float o0 = acc[mt][nt][2] * s1, o1 = acc[mt][nt][3] * s1;
                if (FUSE) {
                    float2 gv = *(const float2*)(G + ro1 + c);
                    o0 *= gv.x / (1.0f + expf(-gv.x));
                    o1 *= gv.y / (1.0f + expf(-gv.y));
                    uint32_t h, l;
                    split_h2(o0, o1, h, l);
                    const size_t wi = (ro1 + c) >> 1;
                    CH[wi] = h; CL[wi] = l;
                } else if (MODE == 2) {
                    atomicAdd(C + ro1 + c, o0);
                    atomicAdd(C + ro1 + c + 1, o1);
                } else {
                    *(float2*)(C + ro1 + c) = make_float2(o0, o1);
                }
            }
        }
    }
}

// ---------------------------------------------------------------------------
// Launch
// ---------------------------------------------------------------------------
extern "C" void kernel_launch(void* const* d_in, const int* in_sizes, int n_in,
                              void* d_out, int out_size) {
    const float* x  = (const float*)d_in[0];
    const float* rw = (const float*)d_in[1];
    const float* eg = (const float*)d_in[2];
    const float* eu = (const float*)d_in[3];
    const float* ed = (const float*)d_in[4];
    const float* sg = (const float*)d_in[5];
    const float* su = (const float*)d_in[6];
    const float* sd = (const float*)d_in[7];
    float* out = (float*)d_out;

#define SYM(p, s) void* p; cudaGetSymbolAddress(&p, s)
    SYM(p_gate_s, g_gate_s); SYM(p_gate_r, g_gate_r);
    SYM(p_xh, g_xh);   SYM(p_xl, g_xl);
    SYM(p_sgh, g_sgh); SYM(p_sgl, g_sgl);
    SYM(p_suh, g_suh); SYM(p_sul, g_sul);
    SYM(p_sdh, g_sdh); SYM(p_sdl, g_sdl);
    SYM(p_egh, g_egh); SYM(p_egl, g_egl);
    SYM(p_euh, g_euh); SYM(p_eul, g_eul);
    SYM(p_edh, g_edh); SYM(p_edl, g_edl);
    SYM(p_ish, g_ish); SYM(p_isl, g_isl);
    SYM(p_irh, g_irh); SYM(p_irl, g_irl);
#undef SYM

    cudaFuncSetAttribute(tgemm_kernel<0, 0>,
                         cudaFuncAttributeMaxDynamicSharedMemorySize, SMEM_DYN);
    cudaFuncSetAttribute(tgemm_kernel<0, 1>,
                         cudaFuncAttributeMaxDynamicSharedMemorySize, SMEM_DYN);
    cudaFuncSetAttribute(tgemm_kernel<1, 0>,
                         cudaFuncAttributeMaxDynamicSharedMemorySize, SMEM_DYN);
    cudaFuncSetAttribute(tgemm_kernel<1, 1>,
                         cudaFuncAttributeMaxDynamicSharedMemorySize, SMEM_DYN);
    cudaFuncSetAttribute(tgemm_kernel<2, 0>,
                         cudaFuncAttributeMaxDynamicSharedMemorySize, SMEM_DYN);

    zero_counts_kernel<<<1, 32>>>();
    router_kernel<<<T_TOK / 4, 128>>>(x, rw);

    // Pre-split. A-side: contiguous. B-side: fragment-pair-major.
    split_contig_kernel<<<(T_TOK * HID / 2 / 4) / 256, 256>>>(
        x, (uint32_t*)p_xh, (uint32_t*)p_xl, T_TOK * HID / 2);
    split_bpair_kernel<<<dim3((HID / 16 * 4 * (FS / 2)) / 256, 1, 1), 256>>>(
        sg, (uint32_t*)p_sgh, (uint32_t*)p_sgl, FS, HID);
    split_bpair_kernel<<<dim3((HID / 16 * 4 * (FS / 2)) / 256, 1, 1), 256>>>(
        su, (uint32_t*)p_suh, (uint32_t*)p_sul, FS, HID);
    split_bpair_kernel<<<dim3((FS / 16 * 4 * (HID / 2)) / 256, 1, 1), 256>>>(
        sd, (uint32_t*)p_sdh, (uint32_t*)p_sdl, HID, FS);
    split_bpair_kernel<<<dim3((HID / 16 * 4 * (FE / 2)) / 256, 1, NE), 256>>>(
        eg, (uint32_t*)p_egh, (uint32_t*)p_egl, FE, HID);
    split_bpair_kernel<<<dim3((HID / 16 * 4 * (FE / 2)) / 256, 1, NE), 256>>>(
        eu, (uint32_t*)p_euh, (uint32_t*)p_eul, FE, HID);
    split_bpair_kernel<<<dim3((FE / 16 * 4 * (HID / 2)) / 256, 1, NE), 256>>>(
        ed, (uint32_t*)p_edh, (uint32_t*)p_edl, HID, FE);

    // Shared expert: gate -> (up, silu fused, split-write) -> down (writes out)
    tgemm_kernel<0, 0><<<dim3(FS / BN, T_TOK / BM, 1), 256, SMEM_DYN>>>(
        (const uint32_t*)p_xh, (const uint32_t*)p_xl,
        (const uint32_t*)p_sgh, (const uint32_t*)p_sgl,
        (float*)p_gate_s, nullptr, nullptr, nullptr, T_TOK, FS, HID);
    tgemm_kernel<0, 1><<<dim3(FS / BN, T_TOK / BM, 1), 256, SMEM_DYN>>>(
        (const uint32_t*)p_xh, (const uint32_t*)p_xl,
        (const uint32_t*)p_suh, (const uint32_t*)p_sul,
        nullptr, (uint32_t*)p_ish, (uint32_t*)p_isl,
        (const float*)p_gate_s, T_TOK, FS, HID);
    tgemm_kernel<0, 0><<<dim3(HID / BN, T_TOK / BM, 1), 256, SMEM_DYN>>>(
        (const uint32_t*)p_ish, (const uint32_t*)p_isl,
        (const uint32_t*)p_sdh, (const uint32_t*)p_sdl,
        out, nullptr, nullptr, nullptr, T_TOK, HID, FS);

    // Routed experts: gate -> (up, silu fused) -> down (atomicAdd into out)
    tgemm_kernel<1, 0><<<dim3(FE / BN, T_TOK / BM, NE), 256, SMEM_DYN>>>(
        (const uint32_t*)p_xh, (const uint32_t*)p_xl,
        (const uint32_t*)p_egh, (const uint32_t*)p_egl,
        (float*)p_gate_r, nullptr, nullptr, nullptr, 0, FE, HID);
    tgemm_kernel<1, 1><<<dim3(FE / BN, T_TOK / BM, NE), 256, SMEM_DYN>>>(
        (const uint32_t*)p_xh, (const uint32_t*)p_xl,
        (const uint32_t*)p_euh, (const uint32_t*)p_eul,
        nullptr, (uint32_t*)p_irh, (uint32_t*)p_irl,
        (const float*)p_gate_r, 0, FE, HID);
    tgemm_kernel<2, 0><<<dim3(HID / BN, T_TOK / BM, NE), 256, SMEM_DYN>>>(
        (const uint32_t*)p_irh, (const uint32_t*)p_irl,
        (const uint32_t*)p_edh, (const uint32_t*)p_edl,
        out, nullptr, nullptr, nullptr, 0, HID, FE);
}

// round 17
// speedup vs baseline: 1.1887x; 1.0206x over previous
#include <cuda_runtime.h>
#include <cuda_fp16.h>
#include <math.h>
#include <stdint.h>

// Problem constants (fixed by the dataset)
#define T_TOK 4096
#define HID   1024
#define NE    16
#define FE    512
#define FS    2048
#define NPAIR (T_TOK * 2)

// ---------------------------------------------------------------------------
// Scratch (all half2-packed words are uint32)
// ---------------------------------------------------------------------------
__device__ float    g_gate_s[(size_t)T_TOK * FS];
__device__ float    g_gate_r[(size_t)NPAIR * FE];
__device__ int      g_cnt[NE];
__device__ int      g_bucket[NE * T_TOK];
__device__ float    g_pw[NPAIR];
// pre-split A-side (rows x K/2 words, k-pair packed)
__device__ uint32_t g_xh[(size_t)T_TOK * HID / 2];
__device__ uint32_t g_xl[(size_t)T_TOK * HID / 2];
// pre-split B-side, FRAGMENT-PAIR-MAJOR: [K/16][4][N][2] words (validated R16)
__device__ uint32_t g_sgh[(size_t)HID / 2 * FS],  g_sgl[(size_t)HID / 2 * FS];
__device__ uint32_t g_suh[(size_t)HID / 2 * FS],  g_sul[(size_t)HID / 2 * FS];
__device__ uint32_t g_sdh[(size_t)FS / 2 * HID],  g_sdl[(size_t)FS / 2 * HID];
__device__ uint32_t g_egh[(size_t)NE * HID / 2 * FE], g_egl[(size_t)NE * HID / 2 * FE];
__device__ uint32_t g_euh[(size_t)NE * HID / 2 * FE], g_eul[(size_t)NE * HID / 2 * FE];
__device__ uint32_t g_edh[(size_t)NE * FE / 2 * HID], g_edl[(size_t)NE * FE / 2 * HID];
// pre-split intermediates (A-side packing, written by FUSE epilogues)
__device__ uint32_t g_ish[(size_t)T_TOK * FS / 2],  g_isl[(size_t)T_TOK * FS / 2];
__device__ uint32_t g_irh[(size_t)NPAIR * FE / 2],  g_irl[(size_t)NPAIR * FE / 2];

// ---------------------------------------------------------------------------
// fp16 hi/lo split (validated R10-R16)
// ---------------------------------------------------------------------------
__device__ __forceinline__ void split_h2(float x, float y,
                                         uint32_t& hi, uint32_t& lo) {
    half hx = __float2half_rn(x);
    half hy = __float2half_rn(y);
    half lx = __float2half_rn(x - __half2float(hx));
    half ly = __float2half_rn(y - __half2float(hy));
    __half2 h = __halves2half2(hx, hy);
    __half2 l = __halves2half2(lx, ly);
    hi = *reinterpret_cast<uint32_t*>(&h);
    lo = *reinterpret_cast<uint32_t*>(&l);
}

__device__ __forceinline__ void mma_f16(float* d,
                                        const uint32_t* a,
                                        const uint32_t* b) {
    asm volatile(
        "mma.sync.aligned.m16n8k16.row.col.f32.f16.f16.f32 "
        "{%0,%1,%2,%3}, {%4,%5,%6,%7}, {%8,%9}, {%0,%1,%2,%3};\n"
        : "+f"(d[0]), "+f"(d[1]), "+f"(d[2]), "+f"(d[3])
        : "r"(a[0]), "r"(a[1]), "r"(a[2]), "r"(a[3]),
          "r"(b[0]), "r"(b[1]));
}

#define LDSM_X4(r0, r1, r2, r3, addr) \
    asm volatile("ldmatrix.sync.aligned.m8n8.x4.shared.b16 {%0,%1,%2,%3}, [%4];" \
                 : "=r"(r0), "=r"(r1), "=r"(r2), "=r"(r3) : "r"(addr))

__device__ __forceinline__ void cp_async16(uint32_t dst, const void* src,
                                           int src_bytes) {
    asm volatile("cp.async.cg.shared.global [%0], [%1], 16, %2;\n"
                 :: "r"(dst), "l"(src), "r"(src_bytes) : "memory");
}
#define CP_COMMIT() asm volatile("cp.async.commit_group;" ::: "memory")
#define CP_WAIT3()  asm volatile("cp.async.wait_group 3;" ::: "memory")

__device__ __forceinline__ uint32_t cvta_smem(const void* p) {
    uint32_t a;
    asm("{ .reg .u64 t; cvta.to.shared.u64 t, %1; cvt.u32.u64 %0, t; }"
        : "=r"(a) : "l"(p));
    return a;
}

// ---------------------------------------------------------------------------
// Splitters (validated R16)
// ---------------------------------------------------------------------------
__global__ void split_contig_kernel(const float* __restrict__ src,
                                    uint32_t* __restrict__ hi,
                                    uint32_t* __restrict__ lo, int nwords) {
    int i = (blockIdx.x * 256 + threadIdx.x) * 4;
    if (i >= nwords) return;
    float2 v0 = ((const float2*)src)[i];
    float2 v1 = ((const float2*)src)[i + 1];
    float2 v2 = ((const float2*)src)[i + 2];
    float2 v3 = ((const float2*)src)[i + 3];
    uint4 h, l;
    split_h2(v0.x, v0.y, h.x, l.x);
    split_h2(v1.x, v1.y, h.y, l.y);
    split_h2(v2.x, v2.y, h.z, l.z);
    split_h2(v3.x, v3.y, h.w, l.w);
    *(uint4*)(hi + i) = h;
    *(uint4*)(lo + i) = l;
}
__global__ void split_bpair_kernel(const float* __restrict__ src,
                                   uint32_t* __restrict__ hi,
                                   uint32_t* __restrict__ lo,
                                   int N, int K) {
    src += (size_t)blockIdx.z * K * N;
    hi  += (size_t)blockIdx.z * (size_t)(K / 2) * N;
    lo  += (size_t)blockIdx.z * (size_t)(K / 2) * N;
    const int nhalf = N >> 1;
    int idx = blockIdx.x * 256 + threadIdx.x;
    if (idx >= (K / 16) * 4 * nhalf) return;
    const int np  = idx % nhalf;
    const int rem = idx / nhalf;
    const int r   = rem & 3;
    const int kt  = rem >> 2;
    const int n   = 2 * np;
    const int k0  = 2 * (8 * kt + r);
    const int k1  = 2 * (8 * kt + r + 4);
    float2 a0 = *(const float2*)(src + (size_t)k0 * N + n);
    float2 a1 = *(const float2*)(src + (size_t)(k0 + 1) * N + n);
    float2 b0 = *(const float2*)(src + (size_t)k1 * N + n);
    float2 b1 = *(const float2*)(src + (size_t)(k1 + 1) * N + n);
    uint4 h, l;
    split_h2(a0.x, a1.x, h.x, l.x);
    split_h2(b0.x, b1.x, h.y, l.y);
    split_h2(a0.y, a1.y, h.z, l.z);
    split_h2(b0.y, b1.y, h.w, l.w);
    const size_t o = ((size_t)(kt * 4 + r) * N + n) * 2;
    *(uint4*)(hi + o) = h;
    *(uint4*)(lo + o) = l;
}

// ---------------------------------------------------------------------------
// Router (validated rounds 1-16)
// ---------------------------------------------------------------------------
__global__ void zero_counts_kernel() {
    if (threadIdx.x < NE) g_cnt[threadIdx.x] = 0;
}

__global__ void router_kernel(const float* __restrict__ x,
                              const float* __restrict__ rw) {
    int warp = threadIdx.x >> 5;
    int lane = threadIdx.x & 31;
    int t = blockIdx.x * (blockDim.x >> 5) + warp;
    if (t >= T_TOK) return;

    float acc[NE];
#pragma unroll
    for (int e = 0; e < NE; e++) acc[e] = 0.0f;

    const float* xr = x + (size_t)t * HID;
    for (int d = lane; d < HID; d += 32) {
        float xv = xr[d];
        const float* r = rw + (size_t)d * NE;
#pragma unroll
        for (int e = 0; e < NE; e++) acc[e] = fmaf(xv, r[e], acc[e]);
    }
#pragma unroll
    for (int e = 0; e < NE; e++) {
#pragma unroll
        for (int off = 16; off; off >>= 1)
            acc[e] += __shfl_xor_sync(0xffffffffu, acc[e], off);
    }

    if (lane == 0) {
        float mx = acc[0];
#pragma unroll
        for (int e = 1; e < NE; e++) mx = fmaxf(mx, acc[e]);
        float p[NE];
        float s = 0.0f;
#pragma unroll
        for (int e = 0; e < NE; e++) { p[e] = expf(acc[e] - mx); s += p[e]; }
        float inv = 1.0f / s;
#pragma unroll
        for (int e = 0; e < NE; e++) p[e] *= inv;

        int   i0 = 0; float w0 = p[0];
#pragma unroll
        for (int e = 1; e < NE; e++) if (p[e] > w0) { w0 = p[e]; i0 = e; }
        int   i1 = -1; float w1 = -1.0f;
#pragma unroll
        for (int e = 0; e < NE; e++)
            if (e != i0 && p[e] > w1) { w1 = p[e]; i1 = e; }

        int pos0 = atomicAdd(&g_cnt[i0], 1);
        g_bucket[i0 * T_TOK + pos0] = 2 * t;
        int pos1 = atomicAdd(&g_cnt[i1], 1);
        g_bucket[i1 * T_TOK + pos1] = 2 * t + 1;
        g_pw[2 * t]     = w0;
        g_pw[2 * t + 1] = w1;
    }
}

// ---------------------------------------------------------------------------
// Tensor GEMM 128x128x16, 256 threads — R16 structure (956us validated).
// CHANGE vs R16: pipeline depth NSTG 4 -> 5, wait_group 2 -> 3 (issue-ahead 4).
// 103.7KB/CTA x 2 CTA = 207KB < 228KB carveout. Slot-reuse safe: issue kt+4
// targets slot (kt-1)%5, computed last iteration, guarded by top-of-loop sync.
// ---------------------------------------------------------------------------
#define BM 128
#define BN 128
#define BK 16
#define A_PAD 12
#define B_ROW 264
#define OFF_AL 1536
#define OFF_BH 3072
#define OFF_BL 4128
#define STAGEF 5184
#define NSTG 5
#define SMEM_DYN (NSTG * STAGEF * 4)

template <int MODE, int FUSE>
__global__ __launch_bounds__(256, 2)
void tgemm_kernel(const uint32_t* __restrict__ Ahg,
                  const uint32_t* __restrict__ Alg,
                  const uint32_t* __restrict__ Bhg,
                  const uint32_t* __restrict__ Blg,
                  float* __restrict__ C,
                  uint32_t* __restrict__ CH,
                  uint32_t* __restrict__ CL,
                  const float* __restrict__ G,
                  int M, int N, int K) {
    const int e = blockIdx.z;
    int m_rows = M;
    const int* rowlist = nullptr;
    if (MODE != 0) {
        m_rows  = g_cnt[e];
        rowlist = g_bucket + e * T_TOK;
        Bhg += (size_t)e * (K / 2) * N;
        Blg += (size_t)e * (K / 2) * N;
    }
    const int m0 = blockIdx.y * BM;
    const int n0 = blockIdx.x * BN;
    if (m0 >= m_rows) return;

    extern __shared__ uint32_t sm[];
    const uint32_t smem_base = cvta_smem(sm);

    const int tid  = threadIdx.x;
    const int lane = tid & 31;
    const int wid  = tid >> 5;
    const int warp_m = wid >> 2;
    const int warp_n = wid & 3;
    const int g  = lane >> 2;
    const int t4 = lane & 3;
    const int mb = warp_m * 64;
    const int nb = warp_n * 32;

    const int KW = K / 2;

    // --- A producer (R13/R16 mapping) ---
    const int am  = tid >> 1;
    const int akq = (tid & 1) * 4;
    // --- B producer: fragment-pair-major (R16) ---
    const int br  = tid >> 6;
    const int bc  = (tid & 63) * 2;

    const int  ar_g = m0 + am;
    const bool av   = ar_g < m_rows;
    const int  aidx = av ? ar_g : 0;
    int rowidx;
    if (MODE == 0)      rowidx = aidx;
    else if (MODE == 1) rowidx = rowlist[aidx] >> 1;
    else                rowidx = rowlist[aidx];
    const uint32_t* ArH = Ahg + (size_t)rowidx * KW + akq;
    const uint32_t* ArL = Alg + (size_t)rowidx * KW + akq;
    const uint32_t* BgH = Bhg + ((size_t)br * N + n0 + bc) * 2;
    const uint32_t* BgL = Blg + ((size_t)br * N + n0 + bc) * 2;
    const int abytes = av ? 16 : 0;

    const uint32_t a_dst = smem_base + (am * A_PAD + akq) * 4;
    const uint32_t b_dst = smem_base + (OFF_BH + br * B_ROW + bc * 2) * 4;
    const int KT = K / BK;
    const size_t b_kt_stride = (size_t)8 * N;

    auto issue_stage = [&](int kt) {
        const uint32_t so = (uint32_t)((kt % NSTG) * (STAGEF * 4));
        const int kw0 = kt * 8;
        cp_async16(a_dst + so,              ArH + kw0, abytes);
        cp_async16(a_dst + so + OFF_AL * 4, ArL + kw0, abytes);
        cp_async16(b_dst + so,                          BgH + (size_t)kt * b_kt_stride, 16);
        cp_async16(b_dst + so + (OFF_BL - OFF_BH) * 4,  BgL + (size_t)kt * b_kt_stride, 16);
    };

    const int sel = lane >> 3;
    const int rr  = lane & 7;
    const uint32_t a_lm_base =
        (uint32_t)(((mb + rr + ((sel & 1) << 3)) * A_PAD + ((sel >> 1) << 2)) * 4);

    issue_stage(0); CP_COMMIT();
    issue_stage(1); CP_COMMIT();
    issue_stage(2); CP_COMMIT();
    issue_stage(3); CP_COMMIT();

    float acc[4][4][4];
#pragma unroll
    for (int i = 0; i < 4; i++)
#pragma unroll
        for (int j = 0; j < 4; j++)
#pragma unroll
            for (int r = 0; r < 4; r++) acc[i][j][r] = 0.0f;

    for (int kt = 0; kt < KT; kt++) {
        CP_WAIT3();
        __syncthreads();
        if (kt + 4 < KT) issue_stage(kt + 4);
        CP_COMMIT();

        const uint32_t stage_b = smem_base + (uint32_t)((kt % NSTG) * (STAGEF * 4));
        const uint32_t* Bh = sm + (kt % NSTG) * STAGEF + OFF_BH;
        const uint32_t* Bl = Bh + (OFF_BL - OFF_BH);

        uint32_t bh[4][2], bl[4][2];
#pragma unroll
        for (int nt = 0; nt < 4; nt++) {
            const int col = nb + nt * 8 + g;
            uint2 hv = *(const uint2*)&Bh[t4 * B_ROW + col * 2];
            uint2 lv = *(const uint2*)&Bl[t4 * B_ROW + col * 2];
            bh[nt][0] = hv.x; bh[nt][1] = hv.y;
            bl[nt][0] = lv.x; bl[nt][1] = lv.y;
        }
#pragma unroll
        for (int mt = 0; mt < 4; mt++) {
            const uint32_t a_addr = stage_b + a_lm_base
                                  + (uint32_t)(mt * 16 * A_PAD * 4);
            uint32_t ah[4], al[4];
            LDSM_X4(ah[0], ah[1], ah[2], ah[3], a_addr);
            LDSM_X4(al[0], al[1], al[2], al[3], a_addr + OFF_AL * 4);
#pragma unroll
            for (int nt = 0; nt < 4; nt++) mma_f16(acc[mt][nt], ah, bh[nt]);
#pragma unroll
            for (int nt = 0; nt < 4; nt++) mma_f16(acc[mt][nt], ah, bl[nt]);
#pragma unroll
            for (int nt = 0; nt < 4; nt++) mma_f16(acc[mt][nt], al, bh[nt]);
        }
    }

    // Epilogue (validated R12-R16)
#pragma unroll
    for (int mt = 0; mt < 4; mt++) {
        const int r0 = m0 + mb + mt * 16 + g;
        const int r1 = r0 + 8;
        size_t ro0 = 0, ro1 = 0;
        bool v0 = r0 < m_rows, v1 = r1 < m_rows;
        float s0 = 1.0f, s1 = 1.0f;
        if (v0) {
            if (MODE == 0) ro0 = (size_t)r0 * N;
            else {
                const int p = rowlist[r0];
                if (MODE == 2) { s0 = g_pw[p]; ro0 = (size_t)(p >> 1) * N; }
                else ro0 = (size_t)p * N;
            }
        }
        if (v1) {
            if (MODE == 0) ro1 = (size_t)r1 * N;
            else {
                const int p = rowlist[r1];
                if (MODE == 2) { s1 = g_pw[p]; ro1 = (size_t)(p >> 1) * N; }
                else ro1 = (size_t)p * N;
            }
        }
#pragma unroll
        for (int nt = 0; nt < 4; nt++) {
            const int c = n0 + nb + nt * 8 + 2 * t4;
            if (v0) {
                float o0 = acc[mt][nt][0] * s0, o1 = acc[mt][nt][1] * s0;
                if (FUSE) {
                    float2 gv = *(const float2*)(G + ro0 + c);
                    o0 *= gv.x / (1.0f + expf(-gv.x));
                    o1 *= gv.y / (1.0f + expf(-gv.y));
                    uint32_t h, l;
                    split_h2(o0, o1, h, l);
                    const size_t wi = (ro0 + c) >> 1;
                    CH[wi] = h; CL[wi] = l;
                } else if (MODE == 2) {
                    atomicAdd(C + ro0 + c, o0);
                    atomicAdd(C + ro0 + c + 1, o1);
                } else {
                    *(float2*)(C + ro0 + c) = make_float2(o0, o1);
                }
            }
            if (v1) {
                float o0 = acc[mt][nt][2] * s1, o1 = acc[mt][nt][3] * s1;
                if (FUSE) {
                    float2 gv = *(const float2*)(G + ro1 + c);
                    o0 *= gv.x / (1.0f + expf(-gv.x));
                    o1 *= gv.y / (1.0f + expf(-gv.y));
                    uint32_t h, l;
                    split_h2(o0, o1, h, l);
                    const size_t wi = (ro1 + c) >> 1;
                    CH[wi] = h; CL[wi] = l;
                } else if (MODE == 2) {
                    atomicAdd(C + ro1 + c, o0);
                    atomicAdd(C + ro1 + c + 1, o1);
                } else {
                    *(float2*)(C + ro1 + c) = make_float2(o0, o1);
                }
            }
        }
    }
}

// ---------------------------------------------------------------------------
// Launch
// ---------------------------------------------------------------------------
extern "C" void kernel_launch(void* const* d_in, const int* in_sizes, int n_in,
                              void* d_out, int out_size) {
    const float* x  = (const float*)d_in[0];
    const float* rw = (const float*)d_in[1];
    const float* eg = (const float*)d_in[2];
    const float* eu = (const float*)d_in[3];
    const float* ed = (const float*)d_in[4];
    const float* sg = (const float*)d_in[5];
    const float* su = (const float*)d_in[6];
    const float* sd = (const float*)d_in[7];
    float* out = (float*)d_out;

#define SYM(p, s) void* p; cudaGetSymbolAddress(&p, s)
    SYM(p_gate_s, g_gate_s); SYM(p_gate_r, g_gate_r);
    SYM(p_xh, g_xh);   SYM(p_xl, g_xl);
    SYM(p_sgh, g_sgh); SYM(p_sgl, g_sgl);
    SYM(p_suh, g_suh); SYM(p_sul, g_sul);
    SYM(p_sdh, g_sdh); SYM(p_sdl, g_sdl);
    SYM(p_egh, g_egh); SYM(p_egl, g_egl);
    SYM(p_euh, g_euh); SYM(p_eul, g_eul);
    SYM(p_edh, g_edh); SYM(p_edl, g_edl);
    SYM(p_ish, g_ish); SYM(p_isl, g_isl);
    SYM(p_irh, g_irh); SYM(p_irl, g_irl);
#undef SYM

    cudaFuncSetAttribute(tgemm_kernel<0, 0>,
                         cudaFuncAttributeMaxDynamicSharedMemorySize, SMEM_DYN);
    cudaFuncSetAttribute(tgemm_kernel<0, 1>,
                         cudaFuncAttributeMaxDynamicSharedMemorySize, SMEM_DYN);
    cudaFuncSetAttribute(tgemm_kernel<1, 0>,
                         cudaFuncAttributeMaxDynamicSharedMemorySize, SMEM_DYN);
    cudaFuncSetAttribute(tgemm_kernel<1, 1>,
                         cudaFuncAttributeMaxDynamicSharedMemorySize, SMEM_DYN);
    cudaFuncSetAttribute(tgemm_kernel<2, 0>,
                         cudaFuncAttributeMaxDynamicSharedMemorySize, SMEM_DYN);

    zero_counts_kernel<<<1, 32>>>();
    router_kernel<<<T_TOK / 4, 128>>>(x, rw);

    split_contig_kernel<<<(T_TOK * HID / 2 / 4) / 256, 256>>>(
        x, (uint32_t*)p_xh, (uint32_t*)p_xl, T_TOK * HID / 2);
    split_bpair_kernel<<<dim3((HID / 16 * 4 * (FS / 2)) / 256, 1, 1), 256>>>(
        sg, (uint32_t*)p_sgh, (uint32_t*)p_sgl, FS, HID);
    split_bpair_kernel<<<dim3((HID / 16 * 4 * (FS / 2)) / 256, 1, 1), 256>>>(
        su, (uint32_t*)p_suh, (uint32_t*)p_sul, FS, HID);
    split_bpair_kernel<<<dim3((FS / 16 * 4 * (HID / 2)) / 256, 1, 1), 256>>>(
        sd, (uint32_t*)p_sdh, (uint32_t*)p_sdl, HID, FS);
    split_bpair_kernel<<<dim3((HID / 16 * 4 * (FE / 2)) / 256, 1, NE), 256>>>(
        eg, (uint32_t*)p_egh, (uint32_t*)p_egl, FE, HID);
    split_bpair_kernel<<<dim3((HID / 16 * 4 * (FE / 2)) / 256, 1, NE), 256>>>(
        eu, (uint32_t*)p_euh, (uint32_t*)p_eul, FE, HID);
    split_bpair_kernel<<<dim3((FE / 16 * 4 * (HID / 2)) / 256, 1, NE), 256>>>(
        ed, (uint32_t*)p_edh, (uint32_t*)p_edl, HID, FE);

    // Shared expert: gate -> (up, silu fused, split-write) -> down (writes out)
    tgemm_kernel<0, 0><<<dim3(FS / BN, T_TOK / BM, 1), 256, SMEM_DYN>>>(
        (const uint32_t*)p_xh, (const uint32_t*)p_xl,
        (const uint32_t*)p_sgh, (const uint32_t*)p_sgl,
        (float*)p_gate_s, nullptr, nullptr, nullptr, T_TOK, FS, HID);
    tgemm_kernel<0, 1><<<dim3(FS / BN, T_TOK / BM, 1), 256, SMEM_DYN>>>(
        (const uint32_t*)p_xh, (const uint32_t*)p_xl,
        (const uint32_t*)p_suh, (const uint32_t*)p_sul,
        nullptr, (uint32_t*)p_ish, (uint32_t*)p_isl,
        (const float*)p_gate_s, T_TOK, FS, HID);
    tgemm_kernel<0, 0><<<dim3(HID / BN, T_TOK / BM, 1), 256, SMEM_DYN>>>(
        (const uint32_t*)p_ish, (const uint32_t*)p_isl,
        (const uint32_t*)p_sdh, (const uint32_t*)p_sdl,
        out, nullptr, nullptr, nullptr, T_TOK, HID, FS);

    // Routed experts: gate -> (up, silu fused) -> down (atomicAdd into out)
    tgemm_kernel<1, 0><<<dim3(FE / BN, T_TOK / BM, NE), 256, SMEM_DYN>>>(
        (const uint32_t*)p_xh, (const uint32_t*)p_xl,
        (const uint32_t*)p_egh, (const uint32_t*)p_egl,
        (float*)p_gate_r, nullptr, nullptr, nullptr, 0, FE, HID);
    tgemm_kernel<1, 1><<<dim3(FE / BN, T_TOK / BM, NE), 256, SMEM_DYN>>>(
        (const uint32_t*)p_xh, (const uint32_t*)p_xl,
        (const uint32_t*)p_euh, (const uint32_t*)p_eul,
        nullptr, (uint32_t*)p_irh, (uint32_t*)p_irl,
        (const float*)p_gate_r, 0, FE, HID);
    tgemm_kernel<2, 0><<<dim3(HID / BN, T_TOK / BM, NE), 256, SMEM_DYN>>>(
        (const uint32_t*)p_irh, (const uint32_t*)p_irl,
        (const uint32_t*)p_edh, (const uint32_t*)p_edl,
        out, nullptr, nullptr, nullptr, 0, HID, FE);
}